// round 1
// baseline (speedup 1.0000x reference)
#include <cuda_runtime.h>
#include <cuda_bf16.h>

// Balloon-Windkessel BOLD, explicit Euler. One thread per simulation (B=16384),
// sequential loop over T=1000 steps. Issue/latency-bound at ~1 warp/SMSP, so:
//  - minimize instructions per step (precomputed reciprocals, approx rcp/ex2)
//  - deep register prefetch of noise (2 chunks = 40 steps ahead) to hide DRAM latency.

#define DT_C        0.01f
#define V0_C        0.02f
#define NOISE_AMP_C 0.01f
#define BATCH_C     16384

__device__ __forceinline__ float fast_rcp(float x) {
    float r; asm("rcp.approx.f32 %0, %1;" : "=f"(r) : "f"(x)); return r;
}
__device__ __forceinline__ float fast_ex2(float x) {
    float r; asm("ex2.approx.f32 %0, %1;" : "=f"(r) : "f"(x)); return r;
}

template<int U>
__global__ __launch_bounds__(128, 1)
void bw_bold_kernel(const float* __restrict__ noise,
                    const float* __restrict__ sigma_p,
                    const float* __restrict__ mu_p,
                    const float* __restrict__ lamb_p,
                    const float* __restrict__ beta_p,
                    const float* __restrict__ psi_p,
                    const float* __restrict__ phi_p,
                    const float* __restrict__ chi_p,
                    float* __restrict__ out,
                    int T, int B)
{
    const int gid = blockIdx.x * blockDim.x + threadIdx.x;
    if (gid >= B) return;

    const float sigma = __ldg(sigma_p);
    const float mu    = __ldg(mu_p);
    const float lamb  = __ldg(lamb_p);
    const float beta  = __ldg(beta_p);
    const float psi   = __ldg(psi_p);
    const float phi   = __ldg(phi_p);
    const float chi   = __ldg(chi_p);

    const float c_vl = DT_C / lamb;            // DT / lambda
    const float ib   = 1.0f / beta;            // 1 / beta
    const float l2mb = log2f(1.0f - beta);     // log2(1 - beta), for (1-beta)^(1/f)

    float s = 0.0f, f = 1.0f, v = 1.0f, q = 1.0f;

    const float* np = noise + gid;
    float*       op = out   + gid;
    const size_t stride = (size_t)B;

    const int nch = T / U;

    // Triple-buffered register prefetch: chunk c computes from b0 while
    // chunk c+2 streams into b2 (load-to-use distance = 2*U steps).
    float b0[U], b1[U], b2[U];
    if (nch > 0) {
        #pragma unroll
        for (int i = 0; i < U; i++) b0[i] = np[(size_t)i * stride];
    }
    if (nch > 1) {
        #pragma unroll
        for (int i = 0; i < U; i++) b1[i] = np[(size_t)(U + i) * stride];
    }

    for (int c = 0; c < nch; c++) {
        const int pc = c + 2;
        if (pc < nch) {
            const float* pp = np + (size_t)pc * U * stride;
            #pragma unroll
            for (int i = 0; i < U; i++) b2[i] = pp[(size_t)i * stride];
        }
        float* o = op + (size_t)c * U * stride;
        #pragma unroll
        for (int i = 0; i < U; i++) {
            const float z = b0[i];
            // E(f) = 1 - (1-beta)^(1/f) = 1 - 2^(log2(1-beta)/f)
            const float E  = 1.0f - fast_ex2(l2mb * fast_rcp(f));
            const float s2 = fmaf(DT_C, fmaf(NOISE_AMP_C, z,
                                      fmaf(-mu, f - 1.0f, -sigma * s)), s);
            const float f2 = fmaf(DT_C, s, f);
            // alpha = 1 -> v^(1/alpha) = v ; v_a*q/v = q
            const float v2 = fmaf(c_vl, f - v, v);
            const float q2 = fmaf(c_vl, fmaf(f * ib, E, -q), q);
            const float rv = fast_rcp(v2);
            const float y  = V0_C * fmaf(phi, 1.0f - q2,
                                  fmaf(psi, fmaf(-q2, rv, 1.0f),
                                       chi * (1.0f - v2)));
            o[(size_t)i * stride] = y;
            s = s2; f = f2; v = v2; q = q2;
        }
        #pragma unroll
        for (int i = 0; i < U; i++) { b0[i] = b1[i]; b1[i] = b2[i]; }
    }

    // Tail (T not divisible by U) — scalar path, direct loads.
    for (int t = nch * U; t < T; t++) {
        const float z  = np[(size_t)t * stride];
        const float E  = 1.0f - fast_ex2(l2mb * fast_rcp(f));
        const float s2 = fmaf(DT_C, fmaf(NOISE_AMP_C, z,
                                  fmaf(-mu, f - 1.0f, -sigma * s)), s);
        const float f2 = fmaf(DT_C, s, f);
        const float v2 = fmaf(c_vl, f - v, v);
        const float q2 = fmaf(c_vl, fmaf(f * ib, E, -q), q);
        const float rv = fast_rcp(v2);
        const float y  = V0_C * fmaf(phi, 1.0f - q2,
                              fmaf(psi, fmaf(-q2, rv, 1.0f),
                                   chi * (1.0f - v2)));
        op[(size_t)t * stride] = y;
        s = s2; f = f2; v = v2; q = q2;
    }
}

extern "C" void kernel_launch(void* const* d_in, const int* in_sizes, int n_in,
                              void* d_out, int out_size)
{
    const float* noise = (const float*)d_in[0];
    const int B = BATCH_C;
    const int T = in_sizes[0] / B;

    const int threads = 128;
    const int blocks  = (B + threads - 1) / threads;

    // U=20 divides T=1000 exactly (50 chunks); 3x20 prefetch regs = 60 regs,
    // irrelevant at this occupancy.
    bw_bold_kernel<20><<<blocks, threads>>>(
        noise,
        (const float*)d_in[1], (const float*)d_in[2],
        (const float*)d_in[3], (const float*)d_in[4],
        (const float*)d_in[5], (const float*)d_in[6],
        (const float*)d_in[7],
        (float*)d_out, T, B);
}

// round 3
// speedup vs baseline: 1.2081x; 1.2081x over previous
#include <cuda_runtime.h>
#include <cuda_bf16.h>

// Balloon-Windkessel BOLD, explicit Euler, T=1000 steps, B=16384 sims.
// One thread per sim (~1 warp/SMSP): per-warp latency/issue bound.
//
// Numerics: per-step arithmetic is BIT-IDENTICAL to the R1 kernel
// (rel_err 1.39e-4). Speed comes only from scheduling:
//  - E, f*ib, f-1, -sigma*s for step t are computed at the END of step t-1
//    (pure functions of already-final state; identical instructions, same
//    values) -> the 36-cycle MUFU chain leaves the carried q-path.
//  - Ping-pong register prefetch with outer loop unrolled by 2 (no MOV
//    rotation), load-to-use distance = 20 steps >> DRAM latency.

#define DT_C        0.01f
#define V0_C        0.02f
#define NOISE_AMP_C 0.01f
#define BATCH_C     16384

__device__ __forceinline__ float fast_rcp(float x) {
    float r; asm("rcp.approx.f32 %0, %1;" : "=f"(r) : "f"(x)); return r;
}
__device__ __forceinline__ float fast_ex2(float x) {
    float r; asm("ex2.approx.f32 %0, %1;" : "=f"(r) : "f"(x)); return r;
}

struct BWState {
    float s, f, v, q;
    // look-ahead values for the CURRENT state (computed when state was produced)
    float E;    // 1 - (1-beta)^(1/f)
    float fib;  // f * (1/beta)
    float fm1;  // f - 1
    float nss;  // -sigma * s
};

struct BWConst {
    float sigma, mu, ib, c_vl, l2mb;
    float psi, phi, chi;
};

// One Euler step. Arithmetic identical to the R1 kernel.
__device__ __forceinline__ float bw_step(BWState& st, const BWConst& C, float z)
{
    // State update using pre-staged pure-function values (same ops as R1):
    const float s2 = fmaf(DT_C, fmaf(NOISE_AMP_C, z,
                              fmaf(-C.mu, st.fm1, st.nss)), st.s);
    const float f2 = fmaf(DT_C, st.s, st.f);
    const float v2 = fmaf(C.c_vl, st.f - st.v, st.v);
    const float q2 = fmaf(C.c_vl, fmaf(st.fib, st.E, -st.q), st.q);

    // Stage look-aheads for the next step (pure functions of s2/f2; these are
    // exactly the instructions R1 executed inside the next step):
    const float rf = fast_rcp(f2);
    st.E   = 1.0f - fast_ex2(C.l2mb * rf);
    st.fib = f2 * C.ib;
    st.fm1 = f2 - 1.0f;
    st.nss = -C.sigma * s2;

    // BOLD readout (identical to R1):
    const float rv = fast_rcp(v2);
    const float y  = V0_C * fmaf(C.phi, 1.0f - q2,
                          fmaf(C.psi, fmaf(-q2, rv, 1.0f),
                               C.chi * (1.0f - v2)));
    st.s = s2; st.f = f2; st.v = v2; st.q = q2;
    return y;
}

template<int U, int BS>
__global__ __launch_bounds__(128, 1)
void bw_bold_kernel(const float* __restrict__ noise,
                    const float* __restrict__ sigma_p,
                    const float* __restrict__ mu_p,
                    const float* __restrict__ lamb_p,
                    const float* __restrict__ beta_p,
                    const float* __restrict__ psi_p,
                    const float* __restrict__ phi_p,
                    const float* __restrict__ chi_p,
                    float* __restrict__ out,
                    int T)
{
    const int gid = blockIdx.x * blockDim.x + threadIdx.x;

    BWConst C;
    C.sigma = __ldg(sigma_p);
    C.mu    = __ldg(mu_p);
    const float lamb = __ldg(lamb_p);
    const float beta = __ldg(beta_p);
    C.psi   = __ldg(psi_p);
    C.phi   = __ldg(phi_p);
    C.chi   = __ldg(chi_p);
    C.c_vl  = DT_C / lamb;
    C.ib    = 1.0f / beta;
    C.l2mb  = log2f(1.0f - beta);

    // Initial state + seed look-aheads (same ops R1 ran in its first step).
    BWState st;
    st.s = 0.0f; st.f = 1.0f; st.v = 1.0f; st.q = 1.0f;
    {
        const float rf = fast_rcp(st.f);
        st.E   = 1.0f - fast_ex2(C.l2mb * rf);
        st.fib = st.f * C.ib;
        st.fm1 = st.f - 1.0f;
        st.nss = -C.sigma * st.s;
    }

    const float* np = noise + gid;
    float*       op = out   + gid;

    const int nch = T / U;

    float bufA[U], bufB[U];
    if (nch > 0) {
        #pragma unroll
        for (int i = 0; i < U; i++) bufA[i] = np[(size_t)i * BS];
    }

    int c = 0;
    for (; c + 1 < nch; c += 2) {
        // Load chunk c+1 into B (used after ~U steps of compute).
        {
            const float* pp = np + (size_t)(c + 1) * U * BS;
            #pragma unroll
            for (int i = 0; i < U; i++) bufB[i] = pp[(size_t)i * BS];
        }
        // Compute chunk c from A.
        {
            float* o = op + (size_t)c * U * BS;
            #pragma unroll
            for (int i = 0; i < U; i++)
                o[(size_t)i * BS] = bw_step(st, C, bufA[i]);
        }
        // Load chunk c+2 into A.
        if (c + 2 < nch) {
            const float* pp = np + (size_t)(c + 2) * U * BS;
            #pragma unroll
            for (int i = 0; i < U; i++) bufA[i] = pp[(size_t)i * BS];
        }
        // Compute chunk c+1 from B.
        {
            float* o = op + (size_t)(c + 1) * U * BS;
            #pragma unroll
            for (int i = 0; i < U; i++)
                o[(size_t)i * BS] = bw_step(st, C, bufB[i]);
        }
    }
    if (c < nch) {  // odd trailing chunk
        float* o = op + (size_t)c * U * BS;
        #pragma unroll
        for (int i = 0; i < U; i++)
            o[(size_t)i * BS] = bw_step(st, C, bufA[i]);
        c++;
    }

    // Tail (T not divisible by U).
    for (int t = nch * U; t < T; t++) {
        const float z = np[(size_t)t * BS];
        op[(size_t)t * BS] = bw_step(st, C, z);
    }
}

extern "C" void kernel_launch(void* const* d_in, const int* in_sizes, int n_in,
                              void* d_out, int out_size)
{
    const float* noise = (const float*)d_in[0];
    const int T = in_sizes[0] / BATCH_C;

    const int threads = 128;
    const int blocks  = BATCH_C / threads;   // 128 blocks x 128 thr = 1 warp/SMSP

    bw_bold_kernel<20, BATCH_C><<<blocks, threads>>>(
        noise,
        (const float*)d_in[1], (const float*)d_in[2],
        (const float*)d_in[3], (const float*)d_in[4],
        (const float*)d_in[5], (const float*)d_in[6],
        (const float*)d_in[7],
        (float*)d_out, T);
}